// round 13
// baseline (speedup 1.0000x reference)
#include <cuda_runtime.h>
#include <cuda_fp16.h>

#define Bb 8
#define Nn 4096
#define Cc 128
#define Kk 20

// ------------------------- scratch (device globals, no allocs) -------------
__device__ int    g_knn[Bb*Nn*Kk];        // 20 neighbor indices per point (global b*N+n space)
__device__ float  g_wT[2*Cc*Cc];          // WcT then WgT, [c][o]
__device__ float  g_center[Bb*Cc*Nn];     // Wc @ leaky(p)         [b][o][n]
__device__ __half g_hT[Bb*Nn*Cc];         // (Wg @ leaky(p))^T in fp16  [b][n][o]
__device__ float4 g_spts4[Bb*Nn];         // x-sorted (x,y,z,|x|^2) per batch
__device__ int    g_sidx[Bb*Nn];          // sorted position -> original index

// ------------------------- prep: transpose weights -------------------------
__global__ __launch_bounds__(256) void prep_kernel(const float* __restrict__ Wc,
                                                   const float* __restrict__ Wg) {
    int t = blockIdx.x * 256 + threadIdx.x;   // 0 .. 2*128*128-1
    int which = t >> 14;                      // 0: Wc, 1: Wg
    int e = t & (Cc*Cc - 1);
    int o = e >> 7, c = e & 127;
    const float* W = which ? Wg : Wc;
    g_wT[which*Cc*Cc + c*Cc + o] = W[o*Cc + c];
}

// ------------------------- sort: bitonic by x, one block per batch ---------
__global__ __launch_bounds__(1024) void sort_kernel(const float* __restrict__ xyz) {
    __shared__ unsigned long long sk[Nn];
    int b = blockIdx.x, tid = threadIdx.x;
    const float* px = xyz + b * 3 * Nn;
    for (int i = tid; i < Nn; i += 1024) {
        unsigned kb = __float_as_uint(px[i]);
        kb = (kb & 0x80000000u) ? ~kb : (kb | 0x80000000u);   // order-preserving
        sk[i] = ((unsigned long long)kb << 32) | (unsigned)i;
    }
    __syncthreads();
    for (int k = 2; k <= Nn; k <<= 1) {
        for (int j = k >> 1; j > 0; j >>= 1) {
            for (int t = tid; t < Nn/2; t += 1024) {
                int i1 = ((t & ~(j-1)) << 1) | (t & (j-1));
                int i2 = i1 | j;
                bool up = ((i1 & k) == 0);
                unsigned long long a = sk[i1], c = sk[i2];
                unsigned long long lo = (a < c) ? a : c;
                unsigned long long hi = (a < c) ? c : a;
                sk[i1] = up ? lo : hi;
                sk[i2] = up ? hi : lo;
            }
            __syncthreads();
        }
    }
    for (int i = tid; i < Nn; i += 1024) {
        int n = (int)(sk[i] & 0xffffffffu);
        float x = px[n], y = px[Nn + n], z = px[2*Nn + n];
        g_spts4[b*Nn + i] = make_float4(x, y, z, fmaf(x, x, fmaf(y, y, z * z)));
        g_sidx[b*Nn + i] = n;
    }
}

// ------------------------- KNN (x-sorted, pruned outward scan) -------------
// 296 blocks (37/batch), 256 thr = 8 warps. Warp takes 16 CONTIGUOUS sorted
// queries (chunk = warp*37 + bib, chunks 0..255 valid; 40 warps idle) ->
// in-warp windows uniform, per-block workload averages over density.
// Lane pair per query: side 0 scans left frontier (i-1-c), side 1 right
// (i+1+c), 8 candidates per round. Side terminates when next dx^2 >=
// worst + |x_i|^2  (exact: sqdist >= dx^2 and |dx| monotone on a side).
// Top-20 (key,pos) in registers via FMNMX/SEL network; R11 staging (C++
// if-stores, depth 20, trigger cnt>=12, vote per round; 11+8=19<20 safe).
// worst shared across the pair via shfl-min (pruned d >= pair-min >= final
// tau). Final pair merge (snapshot + early break); side 0 maps sorted
// positions to original indices via g_sidx and writes.
#define KNN_INF  3.402823466e38f
#define KTHR 256
#define KSTG 20
#define BPB 37

__device__ __forceinline__ void pair_ins20(float (&ds)[20], int (&ix)[20],
                                           float cd, int ci) {
    #pragma unroll
    for (int s = 0; s < 20; ++s) {
        bool t   = cd < ds[s];               // strict: earlier insert wins ties
        float mn = fminf(cd, ds[s]);
        float mx = fmaxf(cd, ds[s]);
        int  ni  = t ? ci : ix[s];
        ci       = t ? ix[s] : ci;
        ds[s] = mn; ix[s] = ni; cd = mx;
    }
}

__device__ __forceinline__ unsigned long long dj_pack(float d, int j) {
    unsigned long long r;
    asm("mov.b64 %0, {%1, %2};" : "=l"(r) : "r"(j), "f"(d));
    return r;
}
__device__ __forceinline__ void dj_unpack(unsigned long long v, float& d, int& j) {
    asm("mov.b64 {%0, %1}, %2;" : "=r"(j), "=f"(d) : "l"(v));
}

__global__ __launch_bounds__(KTHR, 2) void knn_kernel() {
    extern __shared__ float sraw[];
    float4* tile = (float4*)sraw;                              // Nn float4 (64KB)
    unsigned long long* stg = (unsigned long long*)(sraw + Nn*4);  // KTHR*(KSTG+1) u64

    int tid  = threadIdx.x;
    int lane = tid & 31;
    int warp = tid >> 5;
    int side = lane & 1;                               // 0: left, 1: right
    int bib  = blockIdx.x % BPB;
    int b    = blockIdx.x / BPB;
    int chunk = warp * BPB + bib;                      // 0..295; <256 valid
    bool active = chunk < (Nn / 16);

    for (int u = tid; u < Nn; u += KTHR) tile[u] = g_spts4[b*Nn + u];
    __syncthreads();

    int i = (active ? chunk : 0) * 16 + (lane >> 1);   // sorted position of query
    float4 me = tile[i];
    float mx = -2.f * me.x, my = -2.f * me.y, mz = -2.f * me.z;

    float ds[20]; int ix[20];
    #pragma unroll
    for (int s = 0; s < 20; ++s) { ds[s] = KNN_INF; ix[s] = 0; }
    float worst = active ? KNN_INF : -KNN_INF;
    int cnt = 0;
    unsigned long long* st = stg + tid * (KSTG + 1);
    int pos = 0;
    bool done = !active;

    while (__any_sync(0xffffffffu, !done)) {
        if (!done) {
            float dd[8]; int jj[8]; bool qf[8];
            #pragma unroll
            for (int u = 0; u < 8; ++u) {
                int c = pos + u;
                int j = side ? (i + 1 + c) : (i - 1 - c);
                bool oob = (unsigned)j >= (unsigned)Nn;
                float4 p = tile[oob ? i : j];
                float d = fmaf(mx, p.x, fmaf(my, p.y, fmaf(mz, p.z, p.w)));
                dd[u] = oob ? KNN_INF : d;
                jj[u] = j;
                qf[u] = dd[u] < worst;
            }
            int cc = cnt;
            #pragma unroll
            for (int u = 0; u < 8; ++u) {
                if (qf[u]) st[cc] = dj_pack(dd[u], jj[u]);
                cc += qf[u];
            }
            cnt = cc;
            pos += 8;
            // side termination: next |dx|^2 vs sqdist threshold (worst+|xi|^2)
            int jn = side ? (i + 1 + pos) : (i - 1 - pos);
            bool oobn = (unsigned)jn >= (unsigned)Nn;
            float dx = oobn ? 0.f : (tile[jn].x - me.x);
            if (oobn || dx*dx >= worst + me.w) done = true;
        }
        if (__any_sync(0xffffffffu, cnt >= KSTG - 8)) {
            int um = __reduce_max_sync(0xffffffffu, cnt);
            #pragma unroll 1
            for (int u = 0; u < um; ++u) {
                float vd; int vi;
                dj_unpack(st[u], vd, vi);
                pair_ins20(ds, ix, (u < cnt) ? vd : KNN_INF, vi);
            }
            float wm = ds[19];
            float wp = __shfl_xor_sync(0xffffffffu, wm, 1);
            worst = active ? fminf(wm, wp) : -KNN_INF;
            cnt = 0;
        }
    }
    {   // final drain
        int um = __reduce_max_sync(0xffffffffu, cnt);
        #pragma unroll 1
        for (int u = 0; u < um; ++u) {
            float vd; int vi;
            dj_unpack(st[u], vd, vi);
            pair_ins20(ds, ix, (u < cnt) ? vd : KNN_INF, vi);
        }
    }

    // merge lane pair (left + right sides), early break on sorted partner list
    float od[20]; int oi[20];
    #pragma unroll
    for (int s = 0; s < 20; ++s) {
        od[s] = __shfl_xor_sync(0xffffffffu, ds[s], 1);
        oi[s] = __shfl_xor_sync(0xffffffffu, ix[s], 1);
    }
    #pragma unroll 1
    for (int s = 0; s < 20; ++s) {
        if (od[s] >= ds[19]) break;
        pair_ins20(ds, ix, od[s], oi[s]);
    }

    if (side == 0 && active) {
        const int* sx = g_sidx + b * Nn;
        int gq = b * Nn + sx[i];
        #pragma unroll
        for (int s = 0; s < 20; ++s) g_knn[gq*Kk + s] = b * Nn + sx[ix[s]];
    }
}

// ------------------------- fused GEMM: [Wc;Wg] @ leaky(P) ------------------
// grid (N/128, B, 2); z=0 -> center [b][o][n] f32; z=1 -> g_hT [b][n][o] fp16
__global__ __launch_bounds__(256) void gemm_kernel(const float* __restrict__ points) {
    __shared__ __align__(16) float Ws[32][128];   // [c][o]
    __shared__ __align__(16) float Ps[32][128];   // [c][n]
    int b  = blockIdx.y;
    int n0 = blockIdx.x * 128;
    int which = blockIdx.z;
    const float* WT = g_wT + which * Cc * Cc;
    const float* P  = points + b * Cc * Nn;
    int tid = threadIdx.x;
    int tx = tid & 15, ty = tid >> 4;

    unsigned long long acc[8][4];                 // 8 rows x 4 fp32x2 col-pairs
    #pragma unroll
    for (int r = 0; r < 8; ++r)
        #pragma unroll
        for (int q = 0; q < 4; ++q) acc[r][q] = 0ull;

    for (int kc = 0; kc < Cc; kc += 32) {
        __syncthreads();
        #pragma unroll
        for (int i = 0; i < 4; ++i) {
            int f4 = tid + i * 256;               // 0..1023 float4 slots
            int c = f4 >> 5, n4 = f4 & 31;
            *(float4*)&Ws[c][n4*4] = *(const float4*)(WT + (kc + c)*Cc + n4*4);
            float4 pv = *(const float4*)(P + (kc + c)*Nn + n0 + n4*4);
            pv.x = fmaxf(pv.x, 0.f) + 0.01f * fminf(pv.x, 0.f);
            pv.y = fmaxf(pv.y, 0.f) + 0.01f * fminf(pv.y, 0.f);
            pv.z = fmaxf(pv.z, 0.f) + 0.01f * fminf(pv.z, 0.f);
            pv.w = fmaxf(pv.w, 0.f) + 0.01f * fminf(pv.w, 0.f);
            *(float4*)&Ps[c][n4*4] = pv;
        }
        __syncthreads();
        #pragma unroll
        for (int c = 0; c < 32; ++c) {
            float a[8];
            *(float4*)&a[0] = *(float4*)&Ws[c][ty*8];
            *(float4*)&a[4] = *(float4*)&Ws[c][ty*8 + 4];
            unsigned long long bp[4];
            *(ulonglong2*)&bp[0] = *(ulonglong2*)&Ps[c][tx*8];
            *(ulonglong2*)&bp[2] = *(ulonglong2*)&Ps[c][tx*8 + 4];
            #pragma unroll
            for (int r = 0; r < 8; ++r) {
                unsigned long long av;
                asm("mov.b64 %0, {%1, %1};" : "=l"(av) : "f"(a[r]));
                #pragma unroll
                for (int q = 0; q < 4; ++q)
                    asm("fma.rn.f32x2 %0, %1, %2, %0;"
                        : "+l"(acc[r][q]) : "l"(av), "l"(bp[q]));
            }
        }
    }

    union U { unsigned long long u; float2 f; };
    if (which == 0) {
        #pragma unroll
        for (int r = 0; r < 8; ++r) {
            int o = ty*8 + r;
            float v[8];
            #pragma unroll
            for (int q = 0; q < 4; ++q) { U t; t.u = acc[r][q]; v[2*q] = t.f.x; v[2*q+1] = t.f.y; }
            float* dst = g_center + (b*Cc + o)*Nn + n0 + tx*8;
            *(float4*)dst       = make_float4(v[0], v[1], v[2], v[3]);
            *(float4*)(dst + 4) = make_float4(v[4], v[5], v[6], v[7]);
        }
    } else {
        #pragma unroll
        for (int q = 0; q < 4; ++q) {
            float lo[8], hi[8];
            #pragma unroll
            for (int r = 0; r < 8; ++r) { U t; t.u = acc[r][q]; lo[r] = t.f.x; hi[r] = t.f.y; }
            int n = n0 + tx*8 + 2*q;
            union PK { __half2 h2[4]; uint4 u; } p0, p1;
            #pragma unroll
            for (int s = 0; s < 4; ++s) {
                p0.h2[s] = __floats2half2_rn(lo[2*s], lo[2*s+1]);
                p1.h2[s] = __floats2half2_rn(hi[2*s], hi[2*s+1]);
            }
            __half* d0 = g_hT + ((size_t)(b*Nn + n    ))*Cc + ty*8;
            __half* d1 = g_hT + ((size_t)(b*Nn + n + 1))*Cc + ty*8;
            *(uint4*)d0 = p0.u;
            *(uint4*)d1 = p1.u;
        }
    }
}

// ------------------------- combine: gather-sum + center + bias + residual --
__global__ __launch_bounds__(256) void combine_kernel(const float* __restrict__ points,
                                                      const float* __restrict__ bc,
                                                      const float* __restrict__ bg,
                                                      float* __restrict__ out) {
    __shared__ float sm[32][133];     // [n_local][o], pad 133 -> conflict-free transpose
    __shared__ int   sidx[32*20];
    int b  = blockIdx.y;
    int n0 = blockIdx.x * 32;
    int tid = threadIdx.x;

    for (int u = tid; u < 32*20; u += 256)
        sidx[u] = g_knn[(b*Nn + n0)*20 + u];
    __syncthreads();

    // phase A: neighbor gather-sum (fp16 payload, fp32 accumulate)
    int h = tid >> 6, o2 = tid & 63;          // 4 rows in flight, 64 half2-lanes
    for (int nl = h; nl < 32; nl += 4) {
        float ax = 0.f, ay = 0.f;
        #pragma unroll
        for (int k = 0; k < Kk; ++k) {
            int nb = sidx[nl*20 + k];          // global b*N+n index
            __half2 v = *(const __half2*)(g_hT + (size_t)nb*Cc + o2*2);
            float2 f = __half22float2(v);
            ax += f.x; ay += f.y;
        }
        sm[nl][o2*2]     = ax;
        sm[nl][o2*2 + 1] = ay;
    }
    __syncthreads();

    // phase B: transposed, coalesced write with center + bias + shortcut
    int w = tid >> 5, l = tid & 31;
    int n = n0 + l;
    #pragma unroll
    for (int oo = 0; oo < 16; ++oo) {
        int o2b = w + oo*8;
        int off = (b*Cc + o2b)*Nn + n;
        float biasv = fmaf(20.f, bg[o2b], bc[o2b]);
        out[off] = (sm[l][o2b] + g_center[off] + biasv) * (1.0f / 21.0f) + points[off];
    }
}

// ------------------------- launch -----------------------------------------
extern "C" void kernel_launch(void* const* d_in, const int* in_sizes, int n_in,
                              void* d_out, int out_size) {
    const float* xyz    = (const float*)d_in[0];
    const float* points = (const float*)d_in[1];
    const float* Wc     = (const float*)d_in[2];
    const float* bc     = (const float*)d_in[3];
    const float* Wg     = (const float*)d_in[4];
    const float* bg     = (const float*)d_in[5];
    float* out = (float*)d_out;

    int knn_smem = Nn*16 + KTHR*(KSTG+1)*8;
    cudaFuncSetAttribute(knn_kernel, cudaFuncAttributeMaxDynamicSharedMemorySize, knn_smem);

    prep_kernel<<<128, 256>>>(Wc, Wg);
    sort_kernel<<<Bb, 1024>>>(xyz);
    knn_kernel<<<Bb*BPB, KTHR, knn_smem>>>();
    gemm_kernel<<<dim3(Nn/128, Bb, 2), 256>>>(points);
    combine_kernel<<<dim3(Nn/32, Bb), 256>>>(points, bc, bg, out);
}

// round 14
// speedup vs baseline: 1.4736x; 1.4736x over previous
#include <cuda_runtime.h>
#include <cuda_fp16.h>

#define Bb 8
#define Nn 4096
#define Cc 128
#define Kk 20

// ------------------------- scratch (device globals, no allocs) -------------
__device__ int    g_knn[Bb*Nn*Kk];        // 20 neighbor indices per point (global b*N+n space)
__device__ float  g_center[Bb*Cc*Nn];     // Wc @ leaky(p)         [b][o][n]
__device__ __half g_hT[Bb*Nn*Cc];         // (Wg @ leaky(p))^T in fp16  [b][n][o]

// ------------------------- KNN (2 lanes/query, balanced grid) --------------
// R11 version (best known: ~143us). Grid: 37 blocks/batch x 8 = 296 (2/SM
// everywhere). Block: 256 thr = 128 query slots x 2 lanes; QPBLK=111 (last
// block 100); idle slots run worst=-INF. All warp collectives execute on
// uniform control flow; activity gates only result selects. Whole batch tile
// (64KB) in SMEM; lane scans its parity half. Staging: (d,j) packed u64,
// STS.64; depth 20, trigger cnt>=12, vote every 8 (12+8=20 capacity-exact).
// Qualify-flag prefix store addressing. Flush drains reduce_max(cnt) via the
// 21-deep FMNMX/SEL network (invalid -> +INF no-op). worst shared across the
// lane pair via shfl-min. Final pair merge via register snapshot +
// early-break; even lane writes ix[1..20] (slot 0 provably self).
#define KNN_INF  3.402823466e38f
#define KTHR 256
#define KSTG 20
#define QPBLK 111
#define BPB 37

__device__ __forceinline__ void pair_ins(float (&ds)[21], int (&ix)[21],
                                         float cd, int ci) {
    #pragma unroll
    for (int s = 0; s < 21; ++s) {
        bool t   = cd < ds[s];               // strict: earlier insert wins ties
        float mn = fminf(cd, ds[s]);
        float mx = fmaxf(cd, ds[s]);
        int  ni  = t ? ci : ix[s];
        ci       = t ? ix[s] : ci;
        ds[s] = mn; ix[s] = ni; cd = mx;
    }
}

__device__ __forceinline__ unsigned long long dj_pack(float d, int j) {
    unsigned long long r;
    asm("mov.b64 %0, {%1, %2};" : "=l"(r) : "r"(j), "f"(d));
    return r;
}
__device__ __forceinline__ void dj_unpack(unsigned long long v, float& d, int& j) {
    asm("mov.b64 {%0, %1}, %2;" : "=r"(j), "=f"(d) : "l"(v));
}

__global__ __launch_bounds__(KTHR, 2) void knn_kernel(const float* __restrict__ xyz) {
    extern __shared__ float sraw[];
    float4* tile = (float4*)sraw;                              // Nn float4 (64KB)
    unsigned long long* stg = (unsigned long long*)(sraw + Nn*4);  // KTHR*(KSTG+1) u64

    int tid  = threadIdx.x;
    int half = tid & 1;                                // candidate parity
    int qloc = tid >> 1;                               // 0..127 (slots; QPBLK used)
    int bib  = blockIdx.x % BPB;                       // block-in-batch 0..36
    int b    = blockIdx.x / BPB;
    int qstart = bib * QPBLK;
    int qcount = min(QPBLK, Nn - qstart);
    const float* px = xyz + b * 3 * Nn;

    // pack this batch's xyz -> (x,y,z,|x|^2) tile
    for (int n = tid; n < Nn; n += KTHR) {
        float x = px[n], y = px[Nn + n], z = px[2*Nn + n];
        tile[n] = make_float4(x, y, z, fmaf(x, x, fmaf(y, y, z * z)));
    }
    __syncthreads();

    bool active = qloc < qcount;
    int selfn = qstart + (active ? qloc : 0);
    float4 me = tile[selfn];
    float mx = -2.f * me.x, my = -2.f * me.y, mz = -2.f * me.z;

    float ds[21]; int ix[21];
    #pragma unroll
    for (int s = 0; s < 21; ++s) { ds[s] = KNN_INF; ix[s] = 0; }
    float worst = active ? KNN_INF : -KNN_INF;         // idle: never qualifies
    int cnt = 0;
    unsigned long long* st = stg + tid * (KSTG + 1);

    #pragma unroll 1
    for (int i0 = 0; i0 < Nn/2; i0 += 8) {
        // 8 candidates, independent flags, prefix-addressed stores
        float dd[8]; int jj[8]; bool qf[8];
        #pragma unroll
        for (int u = 0; u < 8; ++u) {
            jj[u] = (i0 + u) * 2 + half;
            float4 c = tile[jj[u]];
            dd[u] = fmaf(mx, c.x, fmaf(my, c.y, fmaf(mz, c.z, c.w)));
            qf[u] = dd[u] < worst;
        }
        int cc = cnt;
        #pragma unroll
        for (int u = 0; u < 8; ++u) {
            if (qf[u]) st[cc] = dj_pack(dd[u], jj[u]);
            cc += qf[u];
        }
        cnt = cc;

        if (__any_sync(0xffffffffu, cnt >= KSTG - 8)) {
            int um = __reduce_max_sync(0xffffffffu, cnt);
            #pragma unroll 1
            for (int u = 0; u < um; ++u) {
                float vd; int vi;
                dj_unpack(st[u], vd, vi);
                pair_ins(ds, ix, (u < cnt) ? vd : KNN_INF, vi);
            }
            // collectives unconditional; activity gates only the select
            float wm = ds[20];
            float wp = __shfl_xor_sync(0xffffffffu, wm, 1);
            worst = active ? fminf(wm, wp) : -KNN_INF;
            cnt = 0;
        }
    }
    {   // final drain
        int um = __reduce_max_sync(0xffffffffu, cnt);
        #pragma unroll 1
        for (int u = 0; u < um; ++u) {
            float vd; int vi;
            dj_unpack(st[u], vd, vi);
            pair_ins(ds, ix, (u < cnt) ? vd : KNN_INF, vi);
        }
    }

    // merge lane pair: snapshot partner's sorted list, insert w/ early break
    float od[21]; int oi[21];
    #pragma unroll
    for (int s = 0; s < 21; ++s) {
        od[s] = __shfl_xor_sync(0xffffffffu, ds[s], 1);
        oi[s] = __shfl_xor_sync(0xffffffffu, ix[s], 1);
    }
    #pragma unroll 1
    for (int s = 0; s < 21; ++s) {
        if (od[s] >= ds[20]) break;                    // od sorted: rest can't enter
        pair_ins(ds, ix, od[s], oi[s]);
    }

    if (half == 0 && active) {
        int gq = b * Nn + qstart + qloc;
        int base = b * Nn;
        #pragma unroll
        for (int s = 0; s < 20; ++s) g_knn[gq*Kk + s] = base + ix[s + 1];  // drop self
    }
}

// ------------------------- GEMM via mma.sync (HMMA fp16 -> f32) ------------
// grid (N/128, B, 2); z=0 -> center [b][o][n] f32; z=1 -> g_hT [b][n][o] fp16
// Block 256 thr = 8 warps (2x4): warp tile 64(o) x 32(n); 4x4 frags of
// m16n8k16 per k-step, K=128 in 8 steps. W in smem [o][c] fp16 pad 136
// (A-fragment b32 LDS conflict-free); P transposed+leaky to [n][c] pad 132.
// Fragments loaded as plain b32 LDS (pairs contiguous in k) - no ldmatrix.
// z=1 epilogue stages C through smem (reusing the W region after sync) for
// coalesced uint4 transposed stores.
#define WROW 136
#define PROW 132
#define GEMM_SMEM (128*WROW*2 + 128*PROW*2)

__global__ __launch_bounds__(256) void gemm_kernel(const float* __restrict__ points,
                                                   const float* __restrict__ Wc,
                                                   const float* __restrict__ Wg) {
    extern __shared__ char gsm[];
    __half* Wh = (__half*)gsm;                    // [128][WROW]
    __half* Pt = (__half*)(gsm + 128*WROW*2);     // [128 n][PROW c]
    int b = blockIdx.y, n0 = blockIdx.x * 128, which = blockIdx.z;
    const float* W = which ? Wg : Wc;
    const float* P = points + b * Cc * Nn;
    int tid  = threadIdx.x;
    int lane = tid & 31, warp = tid >> 5;
    int g = lane >> 2, tig = lane & 3;
    int warp_m = warp >> 2, warp_n = warp & 3;    // 2 x 4 warp grid

    // load W [o][c] -> fp16 smem
    #pragma unroll
    for (int i = 0; i < 16; ++i) {
        int v = tid + i * 256;
        int o = v >> 5, c4 = (v & 31) * 4;
        float4 w = *(const float4*)(W + o*Cc + c4);
        __half2* dst = (__half2*)&Wh[o*WROW + c4];
        dst[0] = __floats2half2_rn(w.x, w.y);
        dst[1] = __floats2half2_rn(w.z, w.w);
    }
    // load P [c][n] -> leaky -> Pt [n][c] fp16 (transpose)
    #pragma unroll
    for (int i = 0; i < 16; ++i) {
        int v = tid + i * 256;
        int c = v >> 5, n4 = (v & 31) * 4;
        float4 p = *(const float4*)(P + c*Nn + n0 + n4);
        float f[4] = {p.x, p.y, p.z, p.w};
        #pragma unroll
        for (int u = 0; u < 4; ++u) {
            float pv = fmaxf(f[u], 0.f) + 0.01f * fminf(f[u], 0.f);
            Pt[(n4 + u)*PROW + c] = __float2half(pv);
        }
    }
    __syncthreads();

    float acc[4][4][4];
    #pragma unroll
    for (int mf = 0; mf < 4; ++mf)
        #pragma unroll
        for (int nf = 0; nf < 4; ++nf)
            #pragma unroll
            for (int u = 0; u < 4; ++u) acc[mf][nf][u] = 0.f;

    int o0 = warp_m * 64, nb0 = warp_n * 32;
    #pragma unroll
    for (int ks = 0; ks < 128; ks += 16) {
        unsigned a[4][4], bf[4][2];
        #pragma unroll
        for (int mf = 0; mf < 4; ++mf) {
            const __half* base = &Wh[(o0 + mf*16 + g)*WROW + ks + tig*2];
            a[mf][0] = *(const unsigned*)base;
            a[mf][1] = *(const unsigned*)(base + 8*WROW);
            a[mf][2] = *(const unsigned*)(base + 8);
            a[mf][3] = *(const unsigned*)(base + 8*WROW + 8);
        }
        #pragma unroll
        for (int nf = 0; nf < 4; ++nf) {
            const __half* base = &Pt[(nb0 + nf*8 + g)*PROW + ks + tig*2];
            bf[nf][0] = *(const unsigned*)base;
            bf[nf][1] = *(const unsigned*)(base + 8);
        }
        #pragma unroll
        for (int mf = 0; mf < 4; ++mf)
            #pragma unroll
            for (int nf = 0; nf < 4; ++nf)
                asm volatile(
                    "mma.sync.aligned.m16n8k16.row.col.f32.f16.f16.f32 "
                    "{%0,%1,%2,%3}, {%4,%5,%6,%7}, {%8,%9}, {%0,%1,%2,%3};"
                    : "+f"(acc[mf][nf][0]), "+f"(acc[mf][nf][1]),
                      "+f"(acc[mf][nf][2]), "+f"(acc[mf][nf][3])
                    : "r"(a[mf][0]), "r"(a[mf][1]), "r"(a[mf][2]), "r"(a[mf][3]),
                      "r"(bf[nf][0]), "r"(bf[nf][1]));
    }

    if (which == 0) {
        // c0,c1 at (o, n..n+1); c2,c3 at (o+8, n..n+1)
        #pragma unroll
        for (int mf = 0; mf < 4; ++mf)
            #pragma unroll
            for (int nf = 0; nf < 4; ++nf) {
                int o = o0 + mf*16 + g;
                int n = n0 + nb0 + nf*8 + tig*2;
                float* d0 = g_center + (b*Cc + o    )*Nn + n;
                float* d1 = g_center + (b*Cc + o + 8)*Nn + n;
                *(float2*)d0 = make_float2(acc[mf][nf][0], acc[mf][nf][1]);
                *(float2*)d1 = make_float2(acc[mf][nf][2], acc[mf][nf][3]);
            }
    } else {
        // stage [n][o] fp16 in smem (reuse Wh region), then coalesced copy-out
        __syncthreads();
        __half* Ct = (__half*)gsm;                // [128 n][WROW o]
        #pragma unroll
        for (int mf = 0; mf < 4; ++mf)
            #pragma unroll
            for (int nf = 0; nf < 4; ++nf) {
                int ol = o0 + mf*16 + g;
                int nl = nb0 + nf*8 + tig*2;
                Ct[ nl     *WROW + ol    ] = __float2half(acc[mf][nf][0]);
                Ct[(nl + 1)*WROW + ol    ] = __float2half(acc[mf][nf][1]);
                Ct[ nl     *WROW + ol + 8] = __float2half(acc[mf][nf][2]);
                Ct[(nl + 1)*WROW + ol + 8] = __float2half(acc[mf][nf][3]);
            }
        __syncthreads();
        // 128 rows x 16 uint4; 2 threads per row, 8 uint4 each
        int row = tid >> 1, part = tid & 1;
        __half* dst = g_hT + ((size_t)(b*Nn + n0 + row))*Cc;
        #pragma unroll
        for (int q = 0; q < 8; ++q) {
            int c8 = (part*8 + q)*8;
            *(uint4*)(dst + c8) = *(uint4*)&Ct[row*WROW + c8];
        }
    }
}

// ------------------------- combine: gather-sum + center + bias + residual --
__global__ __launch_bounds__(256) void combine_kernel(const float* __restrict__ points,
                                                      const float* __restrict__ bc,
                                                      const float* __restrict__ bg,
                                                      float* __restrict__ out) {
    __shared__ float sm[32][133];     // [n_local][o], pad 133 -> conflict-free transpose
    __shared__ int   sidx[32*20];
    int b  = blockIdx.y;
    int n0 = blockIdx.x * 32;
    int tid = threadIdx.x;

    for (int u = tid; u < 32*20; u += 256)
        sidx[u] = g_knn[(b*Nn + n0)*20 + u];
    __syncthreads();

    // phase A: neighbor gather-sum (fp16 payload, fp32 accumulate)
    int h = tid >> 6, o2 = tid & 63;          // 4 rows in flight, 64 half2-lanes
    for (int nl = h; nl < 32; nl += 4) {
        float ax = 0.f, ay = 0.f;
        #pragma unroll
        for (int k = 0; k < Kk; ++k) {
            int nb = sidx[nl*20 + k];          // global b*N+n index
            __half2 v = *(const __half2*)(g_hT + (size_t)nb*Cc + o2*2);
            float2 f = __half22float2(v);
            ax += f.x; ay += f.y;
        }
        sm[nl][o2*2]     = ax;
        sm[nl][o2*2 + 1] = ay;
    }
    __syncthreads();

    // phase B: transposed, coalesced write with center + bias + shortcut
    int w = tid >> 5, l = tid & 31;
    int n = n0 + l;
    #pragma unroll
    for (int oo = 0; oo < 16; ++oo) {
        int o2b = w + oo*8;
        int off = (b*Cc + o2b)*Nn + n;
        float biasv = fmaf(20.f, bg[o2b], bc[o2b]);
        out[off] = (sm[l][o2b] + g_center[off] + biasv) * (1.0f / 21.0f) + points[off];
    }
}

// ------------------------- launch -----------------------------------------
extern "C" void kernel_launch(void* const* d_in, const int* in_sizes, int n_in,
                              void* d_out, int out_size) {
    const float* xyz    = (const float*)d_in[0];
    const float* points = (const float*)d_in[1];
    const float* Wc     = (const float*)d_in[2];
    const float* bc     = (const float*)d_in[3];
    const float* Wg     = (const float*)d_in[4];
    const float* bg     = (const float*)d_in[5];
    float* out = (float*)d_out;

    int knn_smem = Nn*16 + KTHR*(KSTG+1)*8;
    cudaFuncSetAttribute(knn_kernel, cudaFuncAttributeMaxDynamicSharedMemorySize, knn_smem);
    cudaFuncSetAttribute(gemm_kernel, cudaFuncAttributeMaxDynamicSharedMemorySize, GEMM_SMEM);

    knn_kernel<<<Bb*BPB, KTHR, knn_smem>>>(xyz);
    gemm_kernel<<<dim3(Nn/128, Bb, 2), 256, GEMM_SMEM>>>(points, Wc, Wg);
    combine_kernel<<<dim3(Nn/32, Bb), 256>>>(points, bc, bg, out);
}